// round 5
// baseline (speedup 1.0000x reference)
#include <cuda_runtime.h>
#include <cstdint>

#define MAXN 50000
#define NRAD 20
#define FCUT 5.0f

typedef unsigned long long ull;

__device__ float g_h[(size_t)MAXN * 64];
__device__ float g_so[(size_t)MAXN * 192];

__device__ __forceinline__ ull pk2(float lo, float hi) {
    ull r; asm("mov.b64 %0, {%1, %2};" : "=l"(r) : "f"(lo), "f"(hi)); return r;
}
__device__ __forceinline__ float2 up2(ull a) {
    float2 f; asm("mov.b64 {%0, %1}, %2;" : "=f"(f.x), "=f"(f.y) : "l"(a)); return f;
}
__device__ __forceinline__ ull ffma2(ull a, ull b, ull c) {
    ull d; asm("fma.rn.f32x2 %0, %1, %2, %3;" : "=l"(d) : "l"(a), "l"(b), "l"(c)); return d;
}
__device__ __forceinline__ ull mul2(ull a, ull b) {
    ull d; asm("mul.rn.f32x2 %0, %1, %2;" : "=l"(d) : "l"(a), "l"(b)); return d;
}
__device__ __forceinline__ void lds2x64(ull &a, ull &b, unsigned addr) {
    asm("ld.shared.v2.b64 {%0, %1}, [%2];" : "=l"(a), "=l"(b) : "r"(addr));
}
__device__ __forceinline__ void red1(float* p, float v) {
    asm volatile("red.global.add.f32 [%0], %1;" :: "l"(p), "f"(v) : "memory");
}
__device__ __forceinline__ float silu_f(float x) {
    return __fdividef(x, 1.0f + __expf(-x));
}

// ---------------------------------------------------------------------------
// Kernel 0: initialize output with node_scalar / node_vector (residual base)
// ---------------------------------------------------------------------------
__global__ void __launch_bounds__(256) k_init(const float4* __restrict__ ns,
                                              const float4* __restrict__ nv,
                                              float4* __restrict__ out,
                                              int n4s, int n4tot) {
    int i = blockIdx.x * 256 + threadIdx.x;
    if (i < n4s)       out[i] = ns[i];
    else if (i < n4tot) out[i] = nv[i - n4s];
}

// ---------------------------------------------------------------------------
// Kernel 1: H = silu(X @ W1 + b1)    (X: N x 64, W1: 64 x 64)
// ---------------------------------------------------------------------------
__global__ void __launch_bounds__(128) k_mlp1(const float* __restrict__ X,
                                              const float* __restrict__ W,
                                              const float* __restrict__ b,
                                              int N) {
    __shared__ __align__(16) float sW[64 * 64];
    int t = threadIdx.x;
    {
        const float4* w4 = (const float4*)W;
        float4* s4 = (float4*)sW;
        #pragma unroll
        for (int i = 0; i < 8; i++) s4[t + i * 128] = w4[t + i * 128];
    }
    __syncthreads();
    int n = blockIdx.x * 128 + t;
    if (n >= N) return;

    ull x2[64];
    const float4* xr = (const float4*)(X + (size_t)n * 64);
    #pragma unroll
    for (int i = 0; i < 16; i++) {
        float4 v = xr[i];
        x2[4*i+0] = pk2(v.x, v.x); x2[4*i+1] = pk2(v.y, v.y);
        x2[4*i+2] = pk2(v.z, v.z); x2[4*i+3] = pk2(v.w, v.w);
    }
    unsigned wb = (unsigned)__cvta_generic_to_shared(sW);
    float* hr = g_h + (size_t)n * 64;

    #pragma unroll 1
    for (int jg = 0; jg < 4; jg++) {
        ull acc[8];
        #pragma unroll
        for (int i = 0; i < 8; i++) {
            int j = jg * 16 + 2 * i;
            acc[i] = pk2(__ldg(b + j), __ldg(b + j + 1));
        }
        unsigned a0 = wb + jg * 16 * 4;
        #pragma unroll
        for (int k = 0; k < 64; k++) {
            ull w0,w1,w2,w3,w4,w5,w6,w7;
            unsigned a = a0 + k * 64 * 4;
            lds2x64(w0, w1, a);      lds2x64(w2, w3, a + 16);
            lds2x64(w4, w5, a + 32); lds2x64(w6, w7, a + 48);
            acc[0]=ffma2(x2[k],w0,acc[0]); acc[1]=ffma2(x2[k],w1,acc[1]);
            acc[2]=ffma2(x2[k],w2,acc[2]); acc[3]=ffma2(x2[k],w3,acc[3]);
            acc[4]=ffma2(x2[k],w4,acc[4]); acc[5]=ffma2(x2[k],w5,acc[5]);
            acc[6]=ffma2(x2[k],w6,acc[6]); acc[7]=ffma2(x2[k],w7,acc[7]);
        }
        float o[16];
        #pragma unroll
        for (int i = 0; i < 8; i++) {
            float2 p = up2(acc[i]);
            o[2*i]   = silu_f(p.x);
            o[2*i+1] = silu_f(p.y);
        }
        float4* hv = (float4*)(hr + jg * 16);
        hv[0] = make_float4(o[0],  o[1],  o[2],  o[3]);
        hv[1] = make_float4(o[4],  o[5],  o[6],  o[7]);
        hv[2] = make_float4(o[8],  o[9],  o[10], o[11]);
        hv[3] = make_float4(o[12], o[13], o[14], o[15]);
    }
}

// ---------------------------------------------------------------------------
// Kernel 2: scalar_out = H @ W2 + b2   (H: N x 64, W2: 64 x 192)
// ---------------------------------------------------------------------------
__global__ void __launch_bounds__(128) k_mlp2(const float* __restrict__ W,
                                              const float* __restrict__ b,
                                              int N) {
    __shared__ __align__(16) float sW[64 * 192];   // 48 KB
    int t = threadIdx.x;
    {
        const float4* w4 = (const float4*)W;
        float4* s4 = (float4*)sW;
        for (int i = t; i < 3072; i += 128) s4[i] = w4[i];
    }
    __syncthreads();
    int n = blockIdx.x * 128 + t;
    if (n >= N) return;

    ull x2[64];
    const float4* xr = (const float4*)(g_h + (size_t)n * 64);
    #pragma unroll
    for (int i = 0; i < 16; i++) {
        float4 v = xr[i];
        x2[4*i+0] = pk2(v.x, v.x); x2[4*i+1] = pk2(v.y, v.y);
        x2[4*i+2] = pk2(v.z, v.z); x2[4*i+3] = pk2(v.w, v.w);
    }
    unsigned wb = (unsigned)__cvta_generic_to_shared(sW);
    float* orow = g_so + (size_t)n * 192;

    #pragma unroll 1
    for (int jg = 0; jg < 12; jg++) {
        ull acc[8];
        #pragma unroll
        for (int i = 0; i < 8; i++) {
            int j = jg * 16 + 2 * i;
            acc[i] = pk2(__ldg(b + j), __ldg(b + j + 1));
        }
        unsigned a0 = wb + jg * 16 * 4;
        #pragma unroll
        for (int k = 0; k < 64; k++) {
            ull w0,w1,w2,w3,w4,w5,w6,w7;
            unsigned a = a0 + k * 192 * 4;
            lds2x64(w0, w1, a);      lds2x64(w2, w3, a + 16);
            lds2x64(w4, w5, a + 32); lds2x64(w6, w7, a + 48);
            acc[0]=ffma2(x2[k],w0,acc[0]); acc[1]=ffma2(x2[k],w1,acc[1]);
            acc[2]=ffma2(x2[k],w2,acc[2]); acc[3]=ffma2(x2[k],w3,acc[3]);
            acc[4]=ffma2(x2[k],w4,acc[4]); acc[5]=ffma2(x2[k],w5,acc[5]);
            acc[6]=ffma2(x2[k],w6,acc[6]); acc[7]=ffma2(x2[k],w7,acc[7]);
        }
        float o[16];
        #pragma unroll
        for (int i = 0; i < 8; i++) {
            float2 p = up2(acc[i]);
            o[2*i] = p.x; o[2*i+1] = p.y;
        }
        float4* ov = (float4*)(orow + jg * 16);
        ov[0] = make_float4(o[0],  o[1],  o[2],  o[3]);
        ov[1] = make_float4(o[4],  o[5],  o[6],  o[7]);
        ov[2] = make_float4(o[8],  o[9],  o[10], o[11]);
        ov[3] = make_float4(o[12], o[13], o[14], o[15]);
    }
}

// ---------------------------------------------------------------------------
// Kernel 3: fused per-edge filter + message + scatter.
// One WARP processes 32 edges per chunk. Each lane owns 6 channels:
//   {lane, lane+32} (gate_state), {lane+64, lane+96} (gate_edge),
//   {lane+128, lane+160} (message_scalar), as 3 f32x2 register pairs.
// Wf column-pairs live in 60 f32x2 registers (loaded once, persistent grid).
// Sins staged per edge in warp-private shared as duplicated (s,s) pairs.
// ---------------------------------------------------------------------------
__global__ void __launch_bounds__(128) k_edge(const int2* __restrict__ edge,
                                              const float* __restrict__ ediff,
                                              const float* __restrict__ edist,
                                              const float* __restrict__ Wf,
                                              const float* __restrict__ bfil,
                                              const float* __restrict__ nvec,
                                              float* __restrict__ out_s,
                                              float* __restrict__ out_v,
                                              int E, int nchunk) {
    // per-warp regions (4 warps / block)
    __shared__ __align__(16) ull  sSin[4][32 * 22];   // 22-ull stride (176B): 16B-aligned rows
    __shared__ ull  sIC[4][32];                       // (ic, ic)
    __shared__ ull  sCut[4][32];                      // (cut, cut)
    __shared__ float sUx[4][32], sUy[4][32], sUz[4][32];
    __shared__ int  sSrc[4][32], sDst[4][32];

    int w = threadIdx.x >> 5, lane = threadIdx.x & 31;

    // Wf column pairs (c, c+32) for c = lane, lane+64, lane+128
    ull wf0[NRAD], wf1[NRAD], wf2[NRAD];
    #pragma unroll
    for (int r = 0; r < NRAD; r++) {
        const float* wr = Wf + r * 192 + lane;
        wf0[r] = pk2(__ldg(wr),       __ldg(wr + 32));
        wf1[r] = pk2(__ldg(wr + 64),  __ldg(wr + 96));
        wf2[r] = pk2(__ldg(wr + 128), __ldg(wr + 160));
    }
    ull bf0 = pk2(__ldg(bfil + lane),       __ldg(bfil + lane + 32));
    ull bf1 = pk2(__ldg(bfil + lane + 64),  __ldg(bfil + lane + 96));
    ull bf2 = pk2(__ldg(bfil + lane + 128), __ldg(bfil + lane + 160));

    unsigned sinBase = (unsigned)__cvta_generic_to_shared(&sSin[w][0]);

    for (int c = blockIdx.x * 4 + w; c < nchunk; c += gridDim.x * 4) {
        int e0 = c * 32;
        int cnt = E - e0; if (cnt > 32) cnt = 32;

        // ---- stage: lane = edge ----
        if (lane < cnt) {
            int e = e0 + lane;
            int2 ed = edge[e];
            float dist = __ldg(edist + e);
            float invd = __fdividef(1.0f, dist);
            float th = dist * (3.14159265358979f / FCUT);
            float s1, c1;
            __sincosf(th, &s1, &c1);
            float cut = (dist < FCUT) ? 0.5f * (c1 + 1.0f) : 0.0f;
            float dx = __ldg(ediff + 3*(size_t)e);
            float dy = __ldg(ediff + 3*(size_t)e + 1);
            float dz = __ldg(ediff + 3*(size_t)e + 2);
            sSrc[w][lane] = ed.y; sDst[w][lane] = ed.x;
            float ic = invd * cut;
            sIC[w][lane]  = pk2(ic, ic);
            sCut[w][lane] = pk2(cut, cut);
            sUx[w][lane] = dx * invd; sUy[w][lane] = dy * invd; sUz[w][lane] = dz * invd;

            float sp = 0.0f, sc = s1, twoc = c1 + c1;
            ull* row = &sSin[w][lane * 22];
            #pragma unroll
            for (int r = 0; r < NRAD; r++) {
                row[r] = pk2(sc, sc);
                float sn = fmaf(twoc, sc, -sp);
                sp = sc; sc = sn;
            }
        }
        __syncwarp();

        // ---- process: all lanes, each edge ----
        #pragma unroll 1
        for (int i = 0; i < cnt; i++) {
            ull a0 = 0, a1 = 0, a2 = 0;
            unsigned sb = sinBase + i * (22 * 8);
            #pragma unroll
            for (int r = 0; r < NRAD; r += 2) {
                ull sA, sB;
                lds2x64(sA, sB, sb + r * 8);
                a0 = ffma2(sA, wf0[r], a0);
                a1 = ffma2(sA, wf1[r], a1);
                a2 = ffma2(sA, wf2[r], a2);
                a0 = ffma2(sB, wf0[r + 1], a0);
                a1 = ffma2(sB, wf1[r + 1], a1);
                a2 = ffma2(sB, wf2[r + 1], a2);
            }
            ull ic2 = sIC[w][i], cut2 = sCut[w][i];
            float2 F0 = up2(ffma2(a0, ic2, mul2(bf0, cut2)));
            float2 F1 = up2(ffma2(a1, ic2, mul2(bf1, cut2)));
            float2 F2 = up2(ffma2(a2, ic2, mul2(bf2, cut2)));

            size_t src = (size_t)(unsigned)sSrc[w][i];
            size_t dst = (size_t)(unsigned)sDst[w][i];
            float ux = sUx[w][i], uy = sUy[w][i], uz = sUz[w][i];

            const float* so = g_so + src * 192 + lane;
            float gsva = F0.x * so[0],   gsvb = F0.y * so[32];
            float geva = F1.x * so[64],  gevb = F1.y * so[96];
            float msa  = F2.x * so[128], msb  = F2.y * so[160];

            float* os = out_s + dst * 64 + lane;
            red1(os,      msa);
            red1(os + 32, msb);

            const float* nv = nvec + src * 192 + lane;
            float* ov = out_v + dst * 192 + lane;
            {
                float na = nv[0], nb = nv[32];
                red1(ov,      fmaf(na, gsva, geva * ux));
                red1(ov + 32, fmaf(nb, gsvb, gevb * ux));
            }
            {
                float na = nv[64], nb = nv[96];
                red1(ov + 64, fmaf(na, gsva, geva * uy));
                red1(ov + 96, fmaf(nb, gsvb, gevb * uy));
            }
            {
                float na = nv[128], nb = nv[160];
                red1(ov + 128, fmaf(na, gsva, geva * uz));
                red1(ov + 160, fmaf(nb, gsvb, gevb * uz));
            }
        }
        __syncwarp();
    }
}

// ---------------------------------------------------------------------------
extern "C" void kernel_launch(void* const* d_in, const int* in_sizes, int n_in,
                              void* d_out, int out_size) {
    const float* node_scalar = (const float*)d_in[0];
    const float* node_vector = (const float*)d_in[1];
    const int2* edge         = (const int2*)d_in[2];
    const float* edge_diff   = (const float*)d_in[3];
    const float* edge_dist   = (const float*)d_in[4];
    const float* W1          = (const float*)d_in[5];
    const float* b1          = (const float*)d_in[6];
    const float* W2          = (const float*)d_in[7];
    const float* b2          = (const float*)d_in[8];
    const float* Wf          = (const float*)d_in[9];
    const float* bf          = (const float*)d_in[10];

    int N = in_sizes[0] / 64;
    int E = in_sizes[2] / 2;

    float* out   = (float*)d_out;
    float* out_v = out + (size_t)N * 64;

    int n4s = N * 16;
    int n4tot = N * 64;

    k_init<<<(n4tot + 255) / 256, 256>>>((const float4*)node_scalar,
                                         (const float4*)node_vector,
                                         (float4*)out, n4s, n4tot);
    k_mlp1<<<(N + 127) / 128, 128>>>(node_scalar, W1, b1, N);
    k_mlp2<<<(N + 127) / 128, 128>>>(W2, b2, N);

    int nchunk = (E + 31) / 32;
    k_edge<<<444, 128>>>(edge, edge_diff, edge_dist, Wf, bf, node_vector,
                         out, out_v, E, nchunk);
}